// round 1
// baseline (speedup 1.0000x reference)
#include <cuda_runtime.h>
#include <cstdint>

#define NN 100000
#define EE 1600000

typedef unsigned long long ull;

// ---------------- scratch (static device globals; no allocations) ----------
__device__ float    g_h[NN * 64];     // current node features (layer output)
__device__ float    g_pq[NN * 128];   // per-node p (cols 0-63) and q (cols 64-127)
__device__ int      g_src[EE];        // int32 source indices
__device__ unsigned g_gmax[64];       // global max (float bits, all values >= 0)
__device__ float    g_c128[128];      // head constant: g @ Wa[64:128] + ba
__device__ int      g_is64;           // edge_index dtype flag

// ---------------- f32x2 helpers (Blackwell packed fp32) --------------------
static __device__ __forceinline__ ull pk2(float x, float y) {
    ull r;
    asm("mov.b64 %0, {%1, %2};" : "=l"(r)
        : "r"(__float_as_uint(x)), "r"(__float_as_uint(y)));
    return r;
}
static __device__ __forceinline__ float2 upk2(ull v) {
    unsigned lo, hi;
    asm("mov.b64 {%0, %1}, %2;" : "=r"(lo), "=r"(hi) : "l"(v));
    return make_float2(__uint_as_float(lo), __uint_as_float(hi));
}
static __device__ __forceinline__ ull ffma2(ull a, ull b, ull c) {
    ull d;
    asm("fma.rn.f32x2 %0, %1, %2, %3;" : "=l"(d) : "l"(a), "l"(b), "l"(c));
    return d;
}

// ---------------- prep: dtype probe + gmax zero -----------------------------
__global__ void detect_kernel(const int* __restrict__ ei) {
    int tid = threadIdx.x;
    if (tid < 64) g_gmax[tid] = 0u;
    if (tid == 0) {
        // int64 layout => odd 32-bit words of src row are all zero (0<=src<1e5).
        // int32 layout => odd words are random src values; P(all 64 zero)~1e-320.
        int zeros = 0;
        for (int i = 0; i < 64; i++)
            if (ei[2 * i + 1] == 0) zeros++;
        g_is64 = (zeros == 64) ? 1 : 0;
    }
}

__global__ void convert_kernel(const int* __restrict__ ei) {
    int e = blockIdx.x * blockDim.x + threadIdx.x;
    if (e < EE) g_src[e] = g_is64 ? ei[2 * e] : ei[e];
}

// ---------------- layer 1: x[N,3] -> pq[N,128] -----------------------------
__global__ void layer1_kernel(const float* __restrict__ x,
                              const float* __restrict__ W1,
                              const float* __restrict__ b1) {
    int tid  = threadIdx.x;
    int t    = tid & 63;
    int node = blockIdx.x * 4 + (tid >> 6);
    if (node >= NN) return;
    float x0 = x[node * 3 + 0], x1 = x[node * 3 + 1], x2 = x[node * 3 + 2];
    float w0 = W1[t],       w1 = W1[64 + t],  w2 = W1[128 + t];
    float w3 = W1[192 + t], w4 = W1[256 + t], w5 = W1[320 + t];
    float q = x0 * w3 + x1 * w4 + x2 * w5;
    float p = b1[t] + x0 * (w0 - w3) + x1 * (w1 - w4) + x2 * (w2 - w5);
    g_pq[node * 128 + t]      = p;
    g_pq[node * 128 + 64 + t] = q;
}

// ---------------- edge max: h_out[i] = relu(p[i] + max_k q[src[i,k]]) -------
__global__ void edge_kernel() {
    int w    = (blockIdx.x * blockDim.x + threadIdx.x) >> 5;
    int lane = threadIdx.x & 31;
    if (w >= NN) return;
    int s = (lane < 16) ? g_src[w * 16 + lane] : 0;
    float2 m = make_float2(-3.402823466e38f, -3.402823466e38f);
    const float* pq = g_pq;
#pragma unroll
    for (int k = 0; k < 16; k++) {
        int j = __shfl_sync(0xffffffffu, s, k);
        float2 v = *(const float2*)(pq + j * 128 + 64 + lane * 2);
        m.x = fmaxf(m.x, v.x);
        m.y = fmaxf(m.y, v.y);
    }
    float2 p = *(const float2*)(pq + w * 128 + lane * 2);
    float2 r;
    r.x = fmaxf(p.x + m.x, 0.f);
    r.y = fmaxf(p.y + m.y, 0.f);
    *(float2*)(g_h + w * 64 + lane * 2) = r;
}

// ---------------- GEMM: g_h[N,64] @ Wc[64,128] (+bias) -> g_pq[N,128] -------
// mode 0: EdgeConv layer. W is [128,64]; build Wc = [W_top - W_bot | W_bot],
//         bias = b on cols 0-63, no relu.
// mode 1: head stage 1. W = Wa (use rows 0-63 as [64][128]); bias = g_c128
//         on all cols; relu at store.
__global__ void __launch_bounds__(256) gemm_kernel(const float* __restrict__ W,
                                                   const float* __restrict__ b,
                                                   int mode) {
    __shared__ __align__(16) float sW[64 * 128];
    __shared__ float sB[128];
    int tid = threadIdx.x;
    if (mode == 0) {
        for (int i = tid; i < 64 * 128; i += 256) {
            int c = i >> 7, tt = i & 127;
            float v = (tt < 64) ? (W[c * 64 + tt] - W[(c + 64) * 64 + tt])
                                : W[(c + 64) * 64 + (tt - 64)];
            sW[i] = v;
        }
        if (tid < 128) sB[tid] = (tid < 64) ? b[tid] : 0.f;
    } else {
        for (int i = tid; i < 64 * 128; i += 256) sW[i] = W[i];
        if (tid < 128) sB[tid] = g_c128[tid];
    }
    __syncthreads();

    int gidx = blockIdx.x * 256 + tid;
    int node = gidx >> 1;
    if (node >= NN) return;
    int half = gidx & 1;

    const float4* inr = (const float4*)(g_h + node * 64);
    const ulonglong2* sWq = (const ulonglong2*)sW;  // 32 ull2 per 128-float row

    ull acc[32];
#pragma unroll
    for (int i = 0; i < 32; i++) acc[i] = 0ull;

#pragma unroll 4
    for (int c4 = 0; c4 < 16; c4++) {
        float4 h4 = inr[c4];
#pragma unroll
        for (int j = 0; j < 4; j++) {
            float hc = (j == 0) ? h4.x : (j == 1) ? h4.y : (j == 2) ? h4.z : h4.w;
            ull a = pk2(hc, hc);
            const ulonglong2* wp = sWq + (c4 * 4 + j) * 32 + half * 16;
#pragma unroll
            for (int t = 0; t < 16; t++) {
                ulonglong2 wv = wp[t];
                acc[2 * t]     = ffma2(a, wv.x, acc[2 * t]);
                acc[2 * t + 1] = ffma2(a, wv.y, acc[2 * t + 1]);
            }
        }
    }

    float* op = g_pq + node * 128 + half * 64;
#pragma unroll
    for (int t = 0; t < 32; t++) {
        float2 v = upk2(acc[t]);
        int tt = half * 64 + 2 * t;
        v.x += sB[tt];
        v.y += sB[tt + 1];
        if (mode == 1) {
            v.x = fmaxf(v.x, 0.f);
            v.y = fmaxf(v.y, 0.f);
        }
        *(float2*)(op + 2 * t) = v;
    }
}

// ---------------- global max over g_h (all values >= 0) --------------------
__global__ void gmax_kernel() {
    float local = 0.f;
    int stride = gridDim.x * blockDim.x;  // multiple of 64
    for (int idx = blockIdx.x * blockDim.x + threadIdx.x; idx < NN * 64; idx += stride)
        local = fmaxf(local, g_h[idx]);
    __shared__ unsigned sm[64];
    if (threadIdx.x < 64) sm[threadIdx.x] = 0u;
    __syncthreads();
    atomicMax(&sm[threadIdx.x & 63], __float_as_uint(local));
    __syncthreads();
    if (threadIdx.x < 64) atomicMax(&g_gmax[threadIdx.x], sm[threadIdx.x]);
}

// ---------------- c128 = ba + g @ Wa[64:128] --------------------------------
__global__ void c128_kernel(const float* __restrict__ Wa,
                            const float* __restrict__ ba) {
    int t = threadIdx.x;  // 128 threads
    float s = ba[t];
#pragma unroll 8
    for (int c = 0; c < 64; c++)
        s += __uint_as_float(g_gmax[c]) * Wa[(64 + c) * 128 + t];
    g_c128[t] = s;
}

// ---------------- head stage 2: out = x + r @ Wb + bb ----------------------
__global__ void head2_kernel(const float* __restrict__ Wb,
                             const float* __restrict__ bb,
                             const float* __restrict__ x,
                             float* __restrict__ out) {
    __shared__ float sWb[384];
    for (int i = threadIdx.x; i < 384; i += 256) sWb[i] = Wb[i];
    __syncthreads();
    int w    = (blockIdx.x * blockDim.x + threadIdx.x) >> 5;
    int lane = threadIdx.x & 31;
    if (w >= NN) return;
    float4 r4 = ((const float4*)(g_pq + w * 128))[lane];
    int t = lane * 4;
    float a0 = r4.x * sWb[t * 3 + 0] + r4.y * sWb[t * 3 + 3] +
               r4.z * sWb[t * 3 + 6] + r4.w * sWb[t * 3 + 9];
    float a1 = r4.x * sWb[t * 3 + 1] + r4.y * sWb[t * 3 + 4] +
               r4.z * sWb[t * 3 + 7] + r4.w * sWb[t * 3 + 10];
    float a2 = r4.x * sWb[t * 3 + 2] + r4.y * sWb[t * 3 + 5] +
               r4.z * sWb[t * 3 + 8] + r4.w * sWb[t * 3 + 11];
#pragma unroll
    for (int off = 16; off > 0; off >>= 1) {
        a0 += __shfl_down_sync(0xffffffffu, a0, off);
        a1 += __shfl_down_sync(0xffffffffu, a1, off);
        a2 += __shfl_down_sync(0xffffffffu, a2, off);
    }
    if (lane == 0) {
        out[w * 3 + 0] = x[w * 3 + 0] + bb[0] + a0;
        out[w * 3 + 1] = x[w * 3 + 1] + bb[1] + a1;
        out[w * 3 + 2] = x[w * 3 + 2] + bb[2] + a2;
    }
}

// ---------------- launch ----------------------------------------------------
extern "C" void kernel_launch(void* const* d_in, const int* in_sizes, int n_in,
                              void* d_out, int out_size) {
    (void)in_sizes; (void)n_in; (void)out_size;
    const float* x  = (const float*)d_in[0];
    const int*   ei = (const int*)d_in[1];
    const float* W1 = (const float*)d_in[2];
    const float* b1 = (const float*)d_in[3];
    const float* Wl[4] = {(const float*)d_in[4], (const float*)d_in[6],
                          (const float*)d_in[8], (const float*)d_in[10]};
    const float* bl[4] = {(const float*)d_in[5], (const float*)d_in[7],
                          (const float*)d_in[9], (const float*)d_in[11]};
    const float* Wa = (const float*)d_in[12];
    const float* ba = (const float*)d_in[13];
    const float* Wb = (const float*)d_in[14];
    const float* bb = (const float*)d_in[15];
    float* out = (float*)d_out;

    detect_kernel<<<1, 64>>>(ei);
    convert_kernel<<<(EE + 255) / 256, 256>>>(ei);

    // Layer 1 (input dim 3)
    layer1_kernel<<<(NN + 3) / 4, 256>>>(x, W1, b1);
    edge_kernel<<<(NN * 32 + 255) / 256, 256>>>();

    // Layers 2-5
    const int gemm_blocks = (2 * NN + 255) / 256;
    for (int l = 0; l < 4; l++) {
        gemm_kernel<<<gemm_blocks, 256>>>(Wl[l], bl[l], 0);
        edge_kernel<<<(NN * 32 + 255) / 256, 256>>>();
    }

    // Global max + head
    gmax_kernel<<<512, 256>>>();
    c128_kernel<<<1, 128>>>(Wa, ba);
    gemm_kernel<<<gemm_blocks, 256>>>(Wa, nullptr, 1);
    head2_kernel<<<(NN * 32 + 255) / 256, 256>>>(Wb, bb, x, out);
}

// round 2
// speedup vs baseline: 1.5650x; 1.5650x over previous
#include <cuda_runtime.h>
#include <cstdint>

#define NN 100000
#define EE 1600000

typedef unsigned long long ull;

// ---------------- scratch (static device globals; no allocations) ----------
__device__ float    g_h[NN * 64];     // current node features (layer output)
__device__ float    g_pq[NN * 128];   // per-node p (cols 0-63) and q (cols 64-127)
__device__ int      g_src[EE];        // int32 source indices
__device__ unsigned g_gmax[64];       // global max (float bits, all values >= 0)
__device__ float    g_c128[128];      // head constant: g @ Wa[64:128] + ba
__device__ int      g_is64;           // edge_index dtype flag

// ---------------- f32x2 helpers (Blackwell packed fp32) --------------------
static __device__ __forceinline__ ull pk2(float x, float y) {
    ull r;
    asm("mov.b64 %0, {%1, %2};" : "=l"(r)
        : "r"(__float_as_uint(x)), "r"(__float_as_uint(y)));
    return r;
}
static __device__ __forceinline__ float2 upk2(ull v) {
    unsigned lo, hi;
    asm("mov.b64 {%0, %1}, %2;" : "=r"(lo), "=r"(hi) : "l"(v));
    return make_float2(__uint_as_float(lo), __uint_as_float(hi));
}
static __device__ __forceinline__ ull ffma2(ull a, ull b, ull c) {
    ull d;
    asm("fma.rn.f32x2 %0, %1, %2, %3;" : "=l"(d) : "l"(a), "l"(b), "l"(c));
    return d;
}

// ---------------- prep: dtype probe (launch #1) -----------------------------
__global__ void detect_kernel(const int* __restrict__ ei) {
    if (threadIdx.x == 0) {
        // int64 layout => odd 32-bit words of src row are all zero (0<=src<1e5).
        int zeros = 0;
        for (int i = 0; i < 64; i++)
            if (ei[2 * i + 1] == 0) zeros++;
        g_is64 = (zeros == 64) ? 1 : 0;
    }
}

// ---------------- zero gmax (launch #2; also shifts gemm to launch #6) ------
__global__ void zerog_kernel() {
    if (threadIdx.x < 64) g_gmax[threadIdx.x] = 0u;
}

__global__ void convert_kernel(const int* __restrict__ ei) {
    int e = blockIdx.x * blockDim.x + threadIdx.x;
    if (e < EE) g_src[e] = g_is64 ? ei[2 * e] : ei[e];
}

// ---------------- layer 1: x[N,3] -> pq[N,128] -----------------------------
__global__ void layer1_kernel(const float* __restrict__ x,
                              const float* __restrict__ W1,
                              const float* __restrict__ b1) {
    int tid  = threadIdx.x;
    int t    = tid & 63;
    int node = blockIdx.x * 4 + (tid >> 6);
    if (node >= NN) return;
    float x0 = x[node * 3 + 0], x1 = x[node * 3 + 1], x2 = x[node * 3 + 2];
    float w0 = W1[t],       w1 = W1[64 + t],  w2 = W1[128 + t];
    float w3 = W1[192 + t], w4 = W1[256 + t], w5 = W1[320 + t];
    float q = x0 * w3 + x1 * w4 + x2 * w5;
    float p = b1[t] + x0 * (w0 - w3) + x1 * (w1 - w4) + x2 * (w2 - w5);
    g_pq[node * 128 + t]      = p;
    g_pq[node * 128 + 64 + t] = q;
}

// ---------------- edge max: h_out[i] = relu(p[i] + max_k q[src[i,k]]) -------
__global__ void edge_kernel() {
    int w    = (blockIdx.x * blockDim.x + threadIdx.x) >> 5;
    int lane = threadIdx.x & 31;
    if (w >= NN) return;
    int s = (lane < 16) ? g_src[w * 16 + lane] : 0;
    float2 m = make_float2(-3.402823466e38f, -3.402823466e38f);
    const float* pq = g_pq;
#pragma unroll
    for (int k = 0; k < 16; k++) {
        int j = __shfl_sync(0xffffffffu, s, k);
        float2 v = *(const float2*)(pq + j * 128 + 64 + lane * 2);
        m.x = fmaxf(m.x, v.x);
        m.y = fmaxf(m.y, v.y);
    }
    float2 p = *(const float2*)(pq + w * 128 + lane * 2);
    float2 r;
    r.x = fmaxf(p.x + m.x, 0.f);
    r.y = fmaxf(p.y + m.y, 0.f);
    *(float2*)(g_h + w * 64 + lane * 2) = r;
}

// ---------------- GEMM: g_h[N,64] @ Wc[64,128] (+bias) -> g_pq[N,128] -------
// Tiling: block = 64 nodes x 128 cols, 256 threads / 8 warps.
//   warp w: node group g = w>>2 (32 nodes, node = lane), quarter q = w&3
//   thread: 16 f32x2 accumulators covering cols [q*32, q*32+32)
// Weights broadcast from smem (all lanes same address -> conflict free).
// h from smem, padded stride 65 (lane = node -> conflict free).
// Output staged through smem (pad 130) -> fully coalesced float2 stores.
// mode 0: EdgeConv layer: Wc = [W_top - W_bot | W_bot], bias b on cols 0-63.
// mode 1: head stage 1:   Wc = Wa rows 0-63, bias g_c128, relu at store.
__global__ void __launch_bounds__(256) gemm_kernel(const float* __restrict__ W,
                                                   const float* __restrict__ b,
                                                   int mode) {
    extern __shared__ float smem[];
    float* sW = smem;           // [64][128]  = 8192 floats
    float* sH = smem + 8192;    // [64][65]   = 4160 floats
    float* sB = smem + 12352;   // [128]
    int tid = threadIdx.x;
    int nb  = blockIdx.x * 64;

    if (mode == 0) {
        for (int i = tid; i < 8192; i += 256) {
            int c = i >> 7, t = i & 127;
            sW[i] = (t < 64) ? (W[c * 64 + t] - W[(c + 64) * 64 + t])
                             : W[(c + 64) * 64 + (t - 64)];
        }
        if (tid < 128) sB[tid] = (tid < 64) ? b[tid] : 0.f;
    } else {
        for (int i = tid; i < 8192; i += 256) sW[i] = W[i];
        if (tid < 128) sB[tid] = g_c128[tid];
    }
    for (int i = tid; i < 4096; i += 256) {
        int n = i >> 6, k = i & 63;
        sH[n * 65 + k] = (nb + n < NN) ? g_h[(nb + n) * 64 + k] : 0.f;
    }
    __syncthreads();

    int lane = tid & 31;
    int w    = tid >> 5;
    int q    = w & 3;
    int g    = w >> 2;
    int nloc = g * 32 + lane;
    const float* hp = sH + nloc * 65;
    const ulonglong2* wp = ((const ulonglong2*)sW) + q * 8;  // 32 ull2 per row

    ull acc[16];
#pragma unroll
    for (int t = 0; t < 16; t++) acc[t] = 0ull;

#pragma unroll 8
    for (int k = 0; k < 64; k++) {
        float hk = hp[k];
        ull a = pk2(hk, hk);
        const ulonglong2* wr = wp + k * 32;
#pragma unroll
        for (int j = 0; j < 8; j++) {
            ulonglong2 wv = wr[j];
            acc[2 * j]     = ffma2(a, wv.x, acc[2 * j]);
            acc[2 * j + 1] = ffma2(a, wv.y, acc[2 * j + 1]);
        }
    }
    __syncthreads();

    // stage results: sOut [64][130] (aliases sW/sH region; sB is untouched)
    float* sOut = smem;
#pragma unroll
    for (int t = 0; t < 16; t++) {
        float2 v = upk2(acc[t]);
        *(float2*)(sOut + nloc * 130 + q * 32 + 2 * t) = v;
    }
    __syncthreads();

    for (int i = tid; i < 4096; i += 256) {   // 64 nodes x 64 float2
        int n = i >> 6, c2 = i & 63;
        if (nb + n >= NN) continue;
        float2 v  = *(float2*)(sOut + n * 130 + 2 * c2);
        float2 bv = *(float2*)(sB + 2 * c2);
        v.x += bv.x;
        v.y += bv.y;
        if (mode == 1) {
            v.x = fmaxf(v.x, 0.f);
            v.y = fmaxf(v.y, 0.f);
        }
        *(float2*)(g_pq + (nb + n) * 128 + 2 * c2) = v;
    }
}

// ---------------- global max over g_h (all values >= 0) --------------------
__global__ void gmax_kernel() {
    float local = 0.f;
    int stride = gridDim.x * blockDim.x;  // multiple of 64
    for (int idx = blockIdx.x * blockDim.x + threadIdx.x; idx < NN * 64; idx += stride)
        local = fmaxf(local, g_h[idx]);
    __shared__ unsigned sm[64];
    if (threadIdx.x < 64) sm[threadIdx.x] = 0u;
    __syncthreads();
    atomicMax(&sm[threadIdx.x & 63], __float_as_uint(local));
    __syncthreads();
    if (threadIdx.x < 64) atomicMax(&g_gmax[threadIdx.x], sm[threadIdx.x]);
}

// ---------------- c128 = ba + g @ Wa[64:128] --------------------------------
__global__ void c128_kernel(const float* __restrict__ Wa,
                            const float* __restrict__ ba) {
    int t = threadIdx.x;  // 128 threads
    float s = ba[t];
#pragma unroll 8
    for (int c = 0; c < 64; c++)
        s += __uint_as_float(g_gmax[c]) * Wa[(64 + c) * 128 + t];
    g_c128[t] = s;
}

// ---------------- head stage 2: out = x + r @ Wb + bb ----------------------
__global__ void head2_kernel(const float* __restrict__ Wb,
                             const float* __restrict__ bb,
                             const float* __restrict__ x,
                             float* __restrict__ out) {
    __shared__ float sWb[384];
    for (int i = threadIdx.x; i < 384; i += 256) sWb[i] = Wb[i];
    __syncthreads();
    int w    = (blockIdx.x * blockDim.x + threadIdx.x) >> 5;
    int lane = threadIdx.x & 31;
    if (w >= NN) return;
    float4 r4 = ((const float4*)(g_pq + w * 128))[lane];
    int t = lane * 4;
    float a0 = r4.x * sWb[t * 3 + 0] + r4.y * sWb[t * 3 + 3] +
               r4.z * sWb[t * 3 + 6] + r4.w * sWb[t * 3 + 9];
    float a1 = r4.x * sWb[t * 3 + 1] + r4.y * sWb[t * 3 + 4] +
               r4.z * sWb[t * 3 + 7] + r4.w * sWb[t * 3 + 10];
    float a2 = r4.x * sWb[t * 3 + 2] + r4.y * sWb[t * 3 + 5] +
               r4.z * sWb[t * 3 + 8] + r4.w * sWb[t * 3 + 11];
#pragma unroll
    for (int off = 16; off > 0; off >>= 1) {
        a0 += __shfl_down_sync(0xffffffffu, a0, off);
        a1 += __shfl_down_sync(0xffffffffu, a1, off);
        a2 += __shfl_down_sync(0xffffffffu, a2, off);
    }
    if (lane == 0) {
        out[w * 3 + 0] = x[w * 3 + 0] + bb[0] + a0;
        out[w * 3 + 1] = x[w * 3 + 1] + bb[1] + a1;
        out[w * 3 + 2] = x[w * 3 + 2] + bb[2] + a2;
    }
}

// ---------------- launch ----------------------------------------------------
extern "C" void kernel_launch(void* const* d_in, const int* in_sizes, int n_in,
                              void* d_out, int out_size) {
    (void)in_sizes; (void)n_in; (void)out_size;
    const float* x  = (const float*)d_in[0];
    const int*   ei = (const int*)d_in[1];
    const float* W1 = (const float*)d_in[2];
    const float* b1 = (const float*)d_in[3];
    const float* Wl[4] = {(const float*)d_in[4], (const float*)d_in[6],
                          (const float*)d_in[8], (const float*)d_in[10]};
    const float* bl[4] = {(const float*)d_in[5], (const float*)d_in[7],
                          (const float*)d_in[9], (const float*)d_in[11]};
    const float* Wa = (const float*)d_in[12];
    const float* ba = (const float*)d_in[13];
    const float* Wb = (const float*)d_in[14];
    const float* bb = (const float*)d_in[15];
    float* out = (float*)d_out;

    static bool attr_set = false;
    const int GEMM_SMEM = 12480 * 4;  // 49,920 bytes
    if (!attr_set) {
        cudaFuncSetAttribute(gemm_kernel,
                             cudaFuncAttributeMaxDynamicSharedMemorySize,
                             GEMM_SMEM);
        attr_set = true;
    }

    detect_kernel<<<1, 32>>>(ei);                       // launch 1
    zerog_kernel<<<1, 64>>>();                          // launch 2
    convert_kernel<<<(EE + 255) / 256, 256>>>(ei);      // launch 3

    // Layer 1 (input dim 3)
    layer1_kernel<<<(NN + 3) / 4, 256>>>(x, W1, b1);    // launch 4
    edge_kernel<<<(NN * 32 + 255) / 256, 256>>>();      // launch 5

    // Layers 2-5
    const int gemm_blocks = (NN + 63) / 64;
    for (int l = 0; l < 4; l++) {
        gemm_kernel<<<gemm_blocks, 256, GEMM_SMEM>>>(Wl[l], bl[l], 0);  // #6 profiled
        edge_kernel<<<(NN * 32 + 255) / 256, 256>>>();
    }

    // Global max + head
    gmax_kernel<<<512, 256>>>();
    c128_kernel<<<1, 128>>>(Wa, ba);
    gemm_kernel<<<gemm_blocks, 256, GEMM_SMEM>>>(Wa, nullptr, 1);
    head2_kernel<<<(NN * 32 + 255) / 256, 256>>>(Wb, bb, x, out);
}

// round 4
// speedup vs baseline: 1.6783x; 1.0724x over previous
#include <cuda_runtime.h>
#include <cuda_bf16.h>
#include <cstdint>

#define NN 100000
#define EE 1600000
#define TILE_M 128
#define NTILES ((NN + TILE_M - 1) / TILE_M)   // 782

typedef uint32_t u32;

// ---------------- scratch (static device globals; no allocations) ----------
__device__ float          g_h[NN * 64];    // current node features
__device__ float          g_pq[NN * 128];  // p (cols 0-63), q (cols 64-127)
__device__ int            g_src[EE];       // int32 source indices
__device__ unsigned       g_gmax[64];      // global max bits (values >= 0)
__device__ float          g_c128[128];     // head constant: g @ Wa[64:128] + ba
__device__ __nv_bfloat16  g_whi[5 * 128 * 64];  // weight hi parts, [n][k] flat
__device__ __nv_bfloat16  g_wlo[5 * 128 * 64];  // weight lo parts

// ---------------- zero gmax ------------------------------------------------
__global__ void zerog_kernel() {
    if (threadIdx.x < 64) g_gmax[threadIdx.x] = 0u;
}

// ---------------- convert (with inline dtype detect) ------------------------
__global__ void convert_kernel(const int* __restrict__ ei) {
    __shared__ int s64;
    if (threadIdx.x == 0) {
        // int64 layout => odd words of src row all zero (0<=src<1e5);
        // int32 layout => P(all 64 zero) ~ 1e-320.
        int z = 0;
        for (int i = 0; i < 64; i++) z += (ei[2 * i + 1] == 0) ? 1 : 0;
        s64 = (z == 64) ? 1 : 0;
    }
    __syncthreads();
    int e = blockIdx.x * blockDim.x + threadIdx.x;
    if (e < EE) g_src[e] = s64 ? ei[2 * e] : ei[e];
}

// ---------------- weight prep: fp32 -> bf16 hi/lo, combined layout ----------
// layers 0-3: Wc[n][k] = (n<64) ? W[k][n] - W[k+64][n] : W[k+64][n-64]
//             (W given as [128 rows k][64 cols n], row-major fan_in x fan_out)
// layer 4:    Wc[n][k] = Wa[k][n]  (Wa is [128][128]; only k<64 used)
__global__ void wprep_kernel(const float* __restrict__ Wl0,
                             const float* __restrict__ Wl1,
                             const float* __restrict__ Wl2,
                             const float* __restrict__ Wl3,
                             const float* __restrict__ Wa) {
    int b = blockIdx.x;
    const float* W = (b == 0) ? Wl0 : (b == 1) ? Wl1 : (b == 2) ? Wl2
                   : (b == 3) ? Wl3 : Wa;
    for (int i = threadIdx.x; i < 8192; i += 256) {
        int n = i >> 6, k = i & 63;
        float wv;
        if (b < 4)
            wv = (n < 64) ? (W[k * 64 + n] - W[(k + 64) * 64 + n])
                          : W[(k + 64) * 64 + (n - 64)];
        else
            wv = W[k * 128 + n];
        __nv_bfloat16 hi = __float2bfloat16(wv);
        __nv_bfloat16 lo = __float2bfloat16(wv - __bfloat162float(hi));
        g_whi[b * 8192 + i] = hi;
        g_wlo[b * 8192 + i] = lo;
    }
}

// ---------------- layer 1: x[N,3] -> pq[N,128] -----------------------------
__global__ void layer1_kernel(const float* __restrict__ x,
                              const float* __restrict__ W1,
                              const float* __restrict__ b1) {
    int tid  = threadIdx.x;
    int t    = tid & 63;
    int node = blockIdx.x * 4 + (tid >> 6);
    if (node >= NN) return;
    float x0 = x[node * 3 + 0], x1 = x[node * 3 + 1], x2 = x[node * 3 + 2];
    float w0 = W1[t],       w1 = W1[64 + t],  w2 = W1[128 + t];
    float w3 = W1[192 + t], w4 = W1[256 + t], w5 = W1[320 + t];
    float q = x0 * w3 + x1 * w4 + x2 * w5;
    float p = b1[t] + x0 * (w0 - w3) + x1 * (w1 - w4) + x2 * (w2 - w5);
    g_pq[node * 128 + t]      = p;
    g_pq[node * 128 + 64 + t] = q;
}

// ---------------- edge max (+ optional fused global max) --------------------
__global__ void edge_kernel(int dogmax) {
    __shared__ unsigned sm[64];
    int w    = (blockIdx.x * blockDim.x + threadIdx.x) >> 5;  // grid exact
    int lane = threadIdx.x & 31;
    int s = (lane < 16) ? g_src[w * 16 + lane] : 0;
    float2 m = make_float2(-3.402823466e38f, -3.402823466e38f);
    const float* pq = g_pq;
#pragma unroll
    for (int k = 0; k < 16; k++) {
        int j = __shfl_sync(0xffffffffu, s, k);
        float2 v = *(const float2*)(pq + j * 128 + 64 + lane * 2);
        m.x = fmaxf(m.x, v.x);
        m.y = fmaxf(m.y, v.y);
    }
    float2 p = *(const float2*)(pq + w * 128 + lane * 2);
    float2 r;
    r.x = fmaxf(p.x + m.x, 0.f);
    r.y = fmaxf(p.y + m.y, 0.f);
    *(float2*)(g_h + w * 64 + lane * 2) = r;
    if (dogmax) {
        if (threadIdx.x < 64) sm[threadIdx.x] = 0u;
        __syncthreads();
        atomicMax(&sm[lane * 2],     __float_as_uint(r.x));   // r >= 0
        atomicMax(&sm[lane * 2 + 1], __float_as_uint(r.y));
        __syncthreads();
        if (threadIdx.x < 64) atomicMax(&g_gmax[threadIdx.x], sm[threadIdx.x]);
    }
}

// ---------------- mma.sync helper -------------------------------------------
static __device__ __forceinline__ void mma16816(float d[4], const u32 a[4],
                                                const u32 b[2]) {
    asm volatile(
        "mma.sync.aligned.m16n8k16.row.col.f32.bf16.bf16.f32 "
        "{%0,%1,%2,%3}, {%4,%5,%6,%7}, {%8,%9}, {%0,%1,%2,%3};"
        : "+f"(d[0]), "+f"(d[1]), "+f"(d[2]), "+f"(d[3])
        : "r"(a[0]), "r"(a[1]), "r"(a[2]), "r"(a[3]), "r"(b[0]), "r"(b[1]));
}

// ---------------- tensor-core GEMM: g_h[N,64] @ Wc[64,128] -> g_pq ----------
// CTA: 128 nodes x 128 cols. 8 warps: warp (wm = wid&3, wn = wid>>2) computes
// a 32(M) x 64(N) tile via m16n8k16 bf16 mma, 3-pass hi/lo split
// (Ahi*Bhi + Ahi*Blo + Alo*Bhi), fp32 accumulate in registers.
// Smem rows padded to 72 bf16 (144B): frag-load bank = 4n+q -> conflict-free.
// mode 0: bias b on cols 0-63.  mode 1: bias g_c128, relu at store.
__global__ void __launch_bounds__(256) tc_gemm_kernel(int layer,
                                                      const float* __restrict__ bias,
                                                      int mode) {
    extern __shared__ unsigned char smem[];
    __nv_bfloat16* sAhi = (__nv_bfloat16*)(smem);             // [128][72]
    __nv_bfloat16* sAlo = (__nv_bfloat16*)(smem + 18432);
    __nv_bfloat16* sBhi = (__nv_bfloat16*)(smem + 36864);
    __nv_bfloat16* sBlo = (__nv_bfloat16*)(smem + 55296);
    float*         sB   = (float*)(smem + 73728);             // bias [128]
    int tid = threadIdx.x;
    int nb  = blockIdx.x * TILE_M;

    // bias
    if (tid < 128)
        sB[tid] = (mode == 0) ? ((tid < 64) ? bias[tid] : 0.f) : g_c128[tid];

    // B: copy pre-split weights into padded smem (u32 = 2 bf16)
    {
        const u32* wh = (const u32*)(g_whi + layer * 8192);
        const u32* wl = (const u32*)(g_wlo + layer * 8192);
        for (int i = tid; i < 4096; i += 256) {
            int n = i >> 5, k2 = (i & 31) * 2;
            *(u32*)(sBhi + n * 72 + k2) = wh[i];
            *(u32*)(sBlo + n * 72 + k2) = wl[i];
        }
    }

    // A: load h tile, split hi/lo
    for (int i = tid; i < 4096; i += 256) {
        int n = i >> 5, k2 = (i & 31) * 2;
        int node = nb + n;
        float2 v = (node < NN) ? *(const float2*)(g_h + node * 64 + k2)
                               : make_float2(0.f, 0.f);
        __nv_bfloat16 h0 = __float2bfloat16(v.x);
        __nv_bfloat16 h1 = __float2bfloat16(v.y);
        __nv_bfloat16 l0 = __float2bfloat16(v.x - __bfloat162float(h0));
        __nv_bfloat16 l1 = __float2bfloat16(v.y - __bfloat162float(h1));
        *(__nv_bfloat162*)(sAhi + n * 72 + k2) = __halves2bfloat162(h0, h1);
        *(__nv_bfloat162*)(sAlo + n * 72 + k2) = __halves2bfloat162(l0, l1);
    }
    __syncthreads();

    int lane = tid & 31;
    int wid  = tid >> 5;
    int wm   = wid & 3;      // M group: rows wm*32..+32
    int wn   = wid >> 2;     // N group: cols wn*64..+64
    int r    = lane >> 2;    // 0..7
    int q    = lane & 3;     // 0..3

    float d[2][8][4];
#pragma unroll
    for (int mt = 0; mt < 2; mt++)
#pragma unroll
        for (int nf = 0; nf < 8; nf++)
#pragma unroll
            for (int j = 0; j < 4; j++) d[mt][nf][j] = 0.f;

#pragma unroll
    for (int pass = 0; pass < 3; pass++) {
        const __nv_bfloat16* A = (pass == 2) ? sAlo : sAhi;
        const __nv_bfloat16* B = (pass == 1) ? sBlo : sBhi;
#pragma unroll
        for (int kk = 0; kk < 4; kk++) {
            int k0 = kk * 16;
            u32 a[2][4];
#pragma unroll
            for (int mt = 0; mt < 2; mt++) {
                const __nv_bfloat16* ap = A + (wm * 32 + mt * 16 + r) * 72 + k0;
                a[mt][0] = *(const u32*)(ap + 2 * q);
                a[mt][1] = *(const u32*)(ap + 8 * 72 + 2 * q);
                a[mt][2] = *(const u32*)(ap + 2 * q + 8);
                a[mt][3] = *(const u32*)(ap + 8 * 72 + 2 * q + 8);
            }
            u32 b[8][2];
#pragma unroll
            for (int nf = 0; nf < 8; nf++) {
                const __nv_bfloat16* bp = B + (wn * 64 + nf * 8 + r) * 72 + k0;
                b[nf][0] = *(const u32*)(bp + 2 * q);
                b[nf][1] = *(const u32*)(bp + 2 * q + 8);
            }
#pragma unroll
            for (int mt = 0; mt < 2; mt++)
#pragma unroll
                for (int nf = 0; nf < 8; nf++)
                    mma16816(d[mt][nf], a[mt], b[nf]);
        }
    }

    // Epilogue: d0,d1 -> (row, col..col+1), d2,d3 -> (row+8, ...)
#pragma unroll
    for (int mt = 0; mt < 2; mt++) {
        int row0 = nb + wm * 32 + mt * 16 + r;
#pragma unroll
        for (int nf = 0; nf < 8; nf++) {
            int col = wn * 64 + nf * 8 + 2 * q;
            float bx = sB[col], by = sB[col + 1];
            float2 v0 = make_float2(d[mt][nf][0] + bx, d[mt][nf][1] + by);
            float2 v1 = make_float2(d[mt][nf][2] + bx, d[mt][nf][3] + by);
            if (mode == 1) {
                v0.x = fmaxf(v0.x, 0.f); v0.y = fmaxf(v0.y, 0.f);
                v1.x = fmaxf(v1.x, 0.f); v1.y = fmaxf(v1.y, 0.f);
            }
            if (row0 < NN)     *(float2*)(g_pq + row0 * 128 + col)       = v0;
            if (row0 + 8 < NN) *(float2*)(g_pq + (row0 + 8) * 128 + col) = v1;
        }
    }
}

// ---------------- c128 = ba + g @ Wa[64:128] --------------------------------
__global__ void c128_kernel(const float* __restrict__ Wa,
                            const float* __restrict__ ba) {
    int t = threadIdx.x;  // 128 threads
    float s = ba[t];
#pragma unroll 8
    for (int c = 0; c < 64; c++)
        s += __uint_as_float(g_gmax[c]) * Wa[(64 + c) * 128 + t];
    g_c128[t] = s;
}

// ---------------- head stage 2: out = x + r @ Wb + bb ----------------------
__global__ void head2_kernel(const float* __restrict__ Wb,
                             const float* __restrict__ bb,
                             const float* __restrict__ x,
                             float* __restrict__ out) {
    __shared__ float sWb[384];
    for (int i = threadIdx.x; i < 384; i += 256) sWb[i] = Wb[i];
    __syncthreads();
    int w    = (blockIdx.x * blockDim.x + threadIdx.x) >> 5;
    int lane = threadIdx.x & 31;
    if (w >= NN) return;
    float4 r4 = ((const float4*)(g_pq + w * 128))[lane];
    int t = lane * 4;
    float a0 = r4.x * sWb[t * 3 + 0] + r4.y * sWb[t * 3 + 3] +
               r4.z * sWb[t * 3 + 6] + r4.w * sWb[t * 3 + 9];
    float a1 = r4.x * sWb[t * 3 + 1] + r4.y * sWb[t * 3 + 4] +
               r4.z * sWb[t * 3 + 7] + r4.w * sWb[t * 3 + 10];
    float a2 = r4.x * sWb[t * 3 + 2] + r4.y * sWb[t * 3 + 5] +
               r4.z * sWb[t * 3 + 8] + r4.w * sWb[t * 3 + 11];
#pragma unroll
    for (int off = 16; off > 0; off >>= 1) {
        a0 += __shfl_down_sync(0xffffffffu, a0, off);
        a1 += __shfl_down_sync(0xffffffffu, a1, off);
        a2 += __shfl_down_sync(0xffffffffu, a2, off);
    }
    if (lane == 0) {
        out[w * 3 + 0] = x[w * 3 + 0] + bb[0] + a0;
        out[w * 3 + 1] = x[w * 3 + 1] + bb[1] + a1;
        out[w * 3 + 2] = x[w * 3 + 2] + bb[2] + a2;
    }
}

// ---------------- launch ----------------------------------------------------
extern "C" void kernel_launch(void* const* d_in, const int* in_sizes, int n_in,
                              void* d_out, int out_size) {
    (void)in_sizes; (void)n_in; (void)out_size;
    const float* x  = (const float*)d_in[0];
    const int*   ei = (const int*)d_in[1];
    const float* W1 = (const float*)d_in[2];
    const float* b1 = (const float*)d_in[3];
    const float* Wl[4] = {(const float*)d_in[4], (const float*)d_in[6],
                          (const float*)d_in[8], (const float*)d_in[10]};
    const float* bl[4] = {(const float*)d_in[5], (const float*)d_in[7],
                          (const float*)d_in[9], (const float*)d_in[11]};
    const float* Wa = (const float*)d_in[12];
    const float* ba = (const float*)d_in[13];
    const float* Wb = (const float*)d_in[14];
    const float* bb = (const float*)d_in[15];
    float* out = (float*)d_out;

    const int GEMM_SMEM = 74240;
    static bool attr_set = false;
    if (!attr_set) {
        cudaFuncSetAttribute(tc_gemm_kernel,
                             cudaFuncAttributeMaxDynamicSharedMemorySize,
                             GEMM_SMEM);
        attr_set = true;
    }

    zerog_kernel<<<1, 64>>>();                                        // #1
    convert_kernel<<<(EE + 255) / 256, 256>>>(ei);                    // #2
    wprep_kernel<<<5, 256>>>(Wl[0], Wl[1], Wl[2], Wl[3], Wa);         // #3
    layer1_kernel<<<(NN + 3) / 4, 256>>>(x, W1, b1);                  // #4
    edge_kernel<<<(NN * 32) / 256, 256>>>(0);                         // #5

    for (int l = 0; l < 4; l++) {
        tc_gemm_kernel<<<NTILES, 256, GEMM_SMEM>>>(l, bl[l], 0);      // #6 (l=0)
        edge_kernel<<<(NN * 32) / 256, 256>>>(l == 3 ? 1 : 0);
    }

    c128_kernel<<<1, 128>>>(Wa, ba);
    tc_gemm_kernel<<<NTILES, 256, GEMM_SMEM>>>(4, ba, 1);
    head2_kernel<<<(NN * 32) / 256, 256>>>(Wb, bb, x, out);
}

// round 5
// speedup vs baseline: 2.2169x; 1.3209x over previous
#include <cuda_runtime.h>
#include <cuda_bf16.h>
#include <cstdint>

#define NN 100000
#define EE 1600000
#define TILE_M 128
#define NTILES ((NN + TILE_M - 1) / TILE_M)   // 782

typedef uint32_t u32;

// ---------------- scratch (static device globals; no allocations) ----------
__device__ float          g_h[NN * 64];    // current node features
__device__ float          g_pq[NN * 128];  // p (cols 0-63), q (cols 64-127)
__device__ int            g_src[EE];       // int32 source indices
__device__ unsigned       g_gmax[64];      // global max bits (values >= 0)
__device__ float          g_c128[128];     // head constant: g @ Wa[64:128] + ba
__device__ __nv_bfloat16  g_whi[5 * 128 * 64];  // weight hi parts, [n][k] flat
__device__ __nv_bfloat16  g_wlo[5 * 128 * 64];  // weight lo parts

// ---------------- convert (fused gmax zero + dtype detect) ------------------
__global__ void convert_kernel(const int* __restrict__ ei) {
    __shared__ int s64;
    if (blockIdx.x == 0 && threadIdx.x < 64) g_gmax[threadIdx.x] = 0u;
    if (threadIdx.x == 0) {
        // int64 layout => odd words of src row all zero (0<=src<1e5);
        // int32 layout => P(all 64 zero) ~ 1e-320.
        int z = 0;
        for (int i = 0; i < 64; i++) z += (ei[2 * i + 1] == 0) ? 1 : 0;
        s64 = (z == 64) ? 1 : 0;
    }
    __syncthreads();
    int e = blockIdx.x * blockDim.x + threadIdx.x;
    if (e < EE) g_src[e] = s64 ? ei[2 * e] : ei[e];
}

// ---------------- layer 1 (nodes) + fused weight prep (last 5 blocks) ------
// wprep: layers 0-3: Wc[n][k] = (n<64) ? W[k][n]-W[k+64][n] : W[k+64][n-64]
//        layer 4:    Wc[n][k] = Wa[k][n]
__global__ void layer1_kernel(const float* __restrict__ x,
                              const float* __restrict__ W1,
                              const float* __restrict__ b1,
                              const float* __restrict__ Wl0,
                              const float* __restrict__ Wl1,
                              const float* __restrict__ Wl2,
                              const float* __restrict__ Wl3,
                              const float* __restrict__ Wa) {
    if (blockIdx.x >= 25000) {
        int b = blockIdx.x - 25000;
        const float* W = (b == 0) ? Wl0 : (b == 1) ? Wl1 : (b == 2) ? Wl2
                       : (b == 3) ? Wl3 : Wa;
        for (int i = threadIdx.x; i < 8192; i += 256) {
            int n = i >> 6, k = i & 63;
            float wv;
            if (b < 4)
                wv = (n < 64) ? (W[k * 64 + n] - W[(k + 64) * 64 + n])
                              : W[(k + 64) * 64 + (n - 64)];
            else
                wv = W[k * 128 + n];
            __nv_bfloat16 hi = __float2bfloat16(wv);
            __nv_bfloat16 lo = __float2bfloat16(wv - __bfloat162float(hi));
            g_whi[b * 8192 + i] = hi;
            g_wlo[b * 8192 + i] = lo;
        }
        return;
    }
    int tid  = threadIdx.x;
    int t    = tid & 63;
    int node = blockIdx.x * 4 + (tid >> 6);
    if (node >= NN) return;
    float x0 = x[node * 3 + 0], x1 = x[node * 3 + 1], x2 = x[node * 3 + 2];
    float w0 = W1[t],       w1 = W1[64 + t],  w2 = W1[128 + t];
    float w3 = W1[192 + t], w4 = W1[256 + t], w5 = W1[320 + t];
    float q = x0 * w3 + x1 * w4 + x2 * w5;
    float p = b1[t] + x0 * (w0 - w3) + x1 * (w1 - w4) + x2 * (w2 - w5);
    g_pq[node * 128 + t]      = p;
    g_pq[node * 128 + 64 + t] = q;
}

// ---------------- edge max (+ optional fused global max) --------------------
__global__ void edge_kernel(int dogmax) {
    __shared__ unsigned sm[64];
    int w    = (blockIdx.x * blockDim.x + threadIdx.x) >> 5;  // grid exact
    int lane = threadIdx.x & 31;
    int s = (lane < 16) ? g_src[w * 16 + lane] : 0;
    float2 m = make_float2(-3.402823466e38f, -3.402823466e38f);
    const float* pq = g_pq;
#pragma unroll
    for (int k = 0; k < 16; k++) {
        int j = __shfl_sync(0xffffffffu, s, k);
        float2 v = *(const float2*)(pq + j * 128 + 64 + lane * 2);
        m.x = fmaxf(m.x, v.x);
        m.y = fmaxf(m.y, v.y);
    }
    float2 p = *(const float2*)(pq + w * 128 + lane * 2);
    float2 r;
    r.x = fmaxf(p.x + m.x, 0.f);
    r.y = fmaxf(p.y + m.y, 0.f);
    *(float2*)(g_h + w * 64 + lane * 2) = r;
    if (dogmax) {
        if (threadIdx.x < 64) sm[threadIdx.x] = 0u;
        __syncthreads();
        atomicMax(&sm[lane * 2],     __float_as_uint(r.x));   // r >= 0
        atomicMax(&sm[lane * 2 + 1], __float_as_uint(r.y));
        __syncthreads();
        if (threadIdx.x < 64) atomicMax(&g_gmax[threadIdx.x], sm[threadIdx.x]);
    }
}

// ---------------- mma / ldmatrix helpers ------------------------------------
static __device__ __forceinline__ void mma16816(float d[4], const u32 a[4],
                                                const u32 b[2]) {
    asm volatile(
        "mma.sync.aligned.m16n8k16.row.col.f32.bf16.bf16.f32 "
        "{%0,%1,%2,%3}, {%4,%5,%6,%7}, {%8,%9}, {%0,%1,%2,%3};"
        : "+f"(d[0]), "+f"(d[1]), "+f"(d[2]), "+f"(d[3])
        : "r"(a[0]), "r"(a[1]), "r"(a[2]), "r"(a[3]), "r"(b[0]), "r"(b[1]));
}
static __device__ __forceinline__ void ldsm4(u32 r[4], u32 addr) {
    asm volatile("ldmatrix.sync.aligned.m8n8.x4.shared.b16 {%0,%1,%2,%3}, [%4];"
        : "=r"(r[0]), "=r"(r[1]), "=r"(r[2]), "=r"(r[3]) : "r"(addr));
}
static __device__ __forceinline__ u32 smem_u32(const void* p) {
    u32 a;
    asm("{ .reg .u64 t; cvta.to.shared.u64 t, %1; cvt.u32.u64 %0, t; }"
        : "=r"(a) : "l"(p));
    return a;
}

// ---------------- tensor-core GEMM: g_h[N,64] @ Wc[64,128] -> g_pq ----------
// Grid = NTILES*2: blockIdx>>1 = node tile (128 rows), blockIdx&1 = N half.
// CTA tile 128M x 64N, 8 warps, warp tile 32M x 32N via m16n8k16 bf16 mma.
// 3-pass hi/lo split: Ahi*Bhi + Alo*Bhi + Ahi*Blo, fp32 accum in regs.
// Fragments loaded with ldmatrix.x4; smem rows padded to 72 bf16 (144 B):
// 8-lane ldmatrix phases hit banks 4r..4r+3 -> conflict-free.
// mode 0: bias on cols 0-63.  mode 1: bias g_c128, relu at store.
__global__ void __launch_bounds__(256) tc_gemm_kernel(int layer,
                                                      const float* __restrict__ bias,
                                                      int mode) {
    extern __shared__ unsigned char smem[];
    __nv_bfloat16* sAhi = (__nv_bfloat16*)(smem);             // [128][72] 18432B
    __nv_bfloat16* sAlo = (__nv_bfloat16*)(smem + 18432);     // 18432B
    __nv_bfloat16* sBhi = (__nv_bfloat16*)(smem + 36864);     // [64][72]  9216B
    __nv_bfloat16* sBlo = (__nv_bfloat16*)(smem + 46080);     // 9216B
    float*         sB   = (float*)(smem + 55296);             // bias [64]
    int tid = threadIdx.x;
    int nb  = (blockIdx.x >> 1) * TILE_M;
    int ny  = blockIdx.x & 1;

    if (tid < 64) {
        int col = ny * 64 + tid;
        sB[tid] = (mode == 0) ? ((col < 64) ? bias[col] : 0.f) : g_c128[col];
    }

    // B: 64 rows of pre-split weights (u32 = 2 bf16)
    {
        const u32* wh = (const u32*)g_whi;
        const u32* wl = (const u32*)g_wlo;
        int base = layer * 4096 + ny * 64 * 32;
        for (int i = tid; i < 2048; i += 256) {
            int n = i >> 5, k2 = i & 31;
            *(u32*)(sBhi + n * 72 + k2 * 2) = wh[base + i];
            *(u32*)(sBlo + n * 72 + k2 * 2) = wl[base + i];
        }
    }

    // A: 128-row h tile, split hi/lo
    for (int i = tid; i < 4096; i += 256) {
        int n = i >> 5, k2 = (i & 31) * 2;
        int node = nb + n;
        float2 v = (node < NN) ? *(const float2*)(g_h + node * 64 + k2)
                               : make_float2(0.f, 0.f);
        __nv_bfloat16 h0 = __float2bfloat16(v.x);
        __nv_bfloat16 h1 = __float2bfloat16(v.y);
        __nv_bfloat16 l0 = __float2bfloat16(v.x - __bfloat162float(h0));
        __nv_bfloat16 l1 = __float2bfloat16(v.y - __bfloat162float(h1));
        *(__nv_bfloat162*)(sAhi + n * 72 + k2) = __halves2bfloat162(h0, h1);
        *(__nv_bfloat162*)(sAlo + n * 72 + k2) = __halves2bfloat162(l0, l1);
    }
    __syncthreads();

    int lane = tid & 31;
    int wid  = tid >> 5;
    int wm   = wid & 3;      // rows wm*32..+32
    int wn   = wid >> 2;     // cols (CTA-local) wn*32..+32

    u32 sbase = smem_u32(smem);
    // A frag addr: rows wm*32 + mt*16 + (lane&15), k-col (lane>>4)*8
    u32 aHi = sbase + ((wm * 32 + (lane & 15)) * 72 + (lane >> 4) * 8) * 2;
    u32 aLo = aHi + 18432;
    // B frag addr: pair p covers 16 n-rows; lanes -> (n sub-row, k half)
    int brow = wn * 32 + (lane & 7) + (lane >> 4) * 8;
    u32 bHi = sbase + 36864 + (brow * 72 + ((lane >> 3) & 1) * 8) * 2;
    u32 bLo = bHi + 9216;

    float d[2][4][4];
#pragma unroll
    for (int mt = 0; mt < 2; mt++)
#pragma unroll
        for (int nf = 0; nf < 4; nf++)
#pragma unroll
            for (int j = 0; j < 4; j++) d[mt][nf][j] = 0.f;

#pragma unroll
    for (int kk = 0; kk < 4; kk++) {
        int ko = kk * 32;  // 16 bf16 = 32 bytes per k-step
        u32 ah[2][4], al[2][4], bb[2][4];
        ldsm4(ah[0], aHi + ko);
        ldsm4(ah[1], aHi + 2304 + ko);         // +16 rows = 16*144 B
        ldsm4(bb[0], bHi + ko);                // nf 0,1
        ldsm4(bb[1], bHi + 2304 + ko);         // nf 2,3
#pragma unroll
        for (int mt = 0; mt < 2; mt++)
#pragma unroll
            for (int nf = 0; nf < 4; nf++)
                mma16816(d[mt][nf], ah[mt], &bb[nf >> 1][(nf & 1) * 2]);
        ldsm4(al[0], aLo + ko);
        ldsm4(al[1], aLo + 2304 + ko);
#pragma unroll
        for (int mt = 0; mt < 2; mt++)
#pragma unroll
            for (int nf = 0; nf < 4; nf++)
                mma16816(d[mt][nf], al[mt], &bb[nf >> 1][(nf & 1) * 2]);
        ldsm4(bb[0], bLo + ko);
        ldsm4(bb[1], bLo + 2304 + ko);
#pragma unroll
        for (int mt = 0; mt < 2; mt++)
#pragma unroll
            for (int nf = 0; nf < 4; nf++)
                mma16816(d[mt][nf], ah[mt], &bb[nf >> 1][(nf & 1) * 2]);
    }

    // Epilogue
    int r = lane >> 2, q = lane & 3;
#pragma unroll
    for (int mt = 0; mt < 2; mt++) {
        int row0 = nb + wm * 32 + mt * 16 + r;
#pragma unroll
        for (int nf = 0; nf < 4; nf++) {
            int ccol = wn * 32 + nf * 8 + 2 * q;
            int gcol = ny * 64 + ccol;
            float bx = sB[ccol], by = sB[ccol + 1];
            float2 v0 = make_float2(d[mt][nf][0] + bx, d[mt][nf][1] + by);
            float2 v1 = make_float2(d[mt][nf][2] + bx, d[mt][nf][3] + by);
            if (mode == 1) {
                v0.x = fmaxf(v0.x, 0.f); v0.y = fmaxf(v0.y, 0.f);
                v1.x = fmaxf(v1.x, 0.f); v1.y = fmaxf(v1.y, 0.f);
            }
            if (row0 < NN)     *(float2*)(g_pq + row0 * 128 + gcol)       = v0;
            if (row0 + 8 < NN) *(float2*)(g_pq + (row0 + 8) * 128 + gcol) = v1;
        }
    }
}

// ---------------- c128 = ba + g @ Wa[64:128] --------------------------------
__global__ void c128_kernel(const float* __restrict__ Wa,
                            const float* __restrict__ ba) {
    int t = threadIdx.x;  // 128 threads
    float s = ba[t];
#pragma unroll 8
    for (int c = 0; c < 64; c++)
        s += __uint_as_float(g_gmax[c]) * Wa[(64 + c) * 128 + t];
    g_c128[t] = s;
}

// ---------------- head stage 2: out = x + r @ Wb + bb ----------------------
__global__ void head2_kernel(const float* __restrict__ Wb,
                             const float* __restrict__ bb,
                             const float* __restrict__ x,
                             float* __restrict__ out) {
    __shared__ float sWb[384];
    for (int i = threadIdx.x; i < 384; i += 256) sWb[i] = Wb[i];
    __syncthreads();
    int w    = (blockIdx.x * blockDim.x + threadIdx.x) >> 5;
    int lane = threadIdx.x & 31;
    if (w >= NN) return;
    float4 r4 = ((const float4*)(g_pq + w * 128))[lane];
    int t = lane * 4;
    float a0 = r4.x * sWb[t * 3 + 0] + r4.y * sWb[t * 3 + 3] +
               r4.z * sWb[t * 3 + 6] + r4.w * sWb[t * 3 + 9];
    float a1 = r4.x * sWb[t * 3 + 1] + r4.y * sWb[t * 3 + 4] +
               r4.z * sWb[t * 3 + 7] + r4.w * sWb[t * 3 + 10];
    float a2 = r4.x * sWb[t * 3 + 2] + r4.y * sWb[t * 3 + 5] +
               r4.z * sWb[t * 3 + 8] + r4.w * sWb[t * 3 + 11];
#pragma unroll
    for (int off = 16; off > 0; off >>= 1) {
        a0 += __shfl_down_sync(0xffffffffu, a0, off);
        a1 += __shfl_down_sync(0xffffffffu, a1, off);
        a2 += __shfl_down_sync(0xffffffffu, a2, off);
    }
    if (lane == 0) {
        out[w * 3 + 0] = x[w * 3 + 0] + bb[0] + a0;
        out[w * 3 + 1] = x[w * 3 + 1] + bb[1] + a1;
        out[w * 3 + 2] = x[w * 3 + 2] + bb[2] + a2;
    }
}

// ---------------- launch ----------------------------------------------------
extern "C" void kernel_launch(void* const* d_in, const int* in_sizes, int n_in,
                              void* d_out, int out_size) {
    (void)in_sizes; (void)n_in; (void)out_size;
    const float* x  = (const float*)d_in[0];
    const int*   ei = (const int*)d_in[1];
    const float* W1 = (const float*)d_in[2];
    const float* b1 = (const float*)d_in[3];
    const float* Wl[4] = {(const float*)d_in[4], (const float*)d_in[6],
                          (const float*)d_in[8], (const float*)d_in[10]};
    const float* bl[4] = {(const float*)d_in[5], (const float*)d_in[7],
                          (const float*)d_in[9], (const float*)d_in[11]};
    const float* Wa = (const float*)d_in[12];
    const float* ba = (const float*)d_in[13];
    const float* Wb = (const float*)d_in[14];
    const float* bb = (const float*)d_in[15];
    float* out = (float*)d_out;

    const int GEMM_SMEM = 55552;
    static bool attr_set = false;
    if (!attr_set) {
        cudaFuncSetAttribute(tc_gemm_kernel,
                             cudaFuncAttributeMaxDynamicSharedMemorySize,
                             GEMM_SMEM);
        attr_set = true;
    }

    convert_kernel<<<(EE + 255) / 256, 256>>>(ei);                        // #1
    layer1_kernel<<<25005, 256>>>(x, W1, b1, Wl[0], Wl[1], Wl[2], Wl[3], Wa); // #2
    edge_kernel<<<(NN * 32) / 256, 256>>>(0);                             // #3

    for (int l = 0; l < 4; l++) {
        tc_gemm_kernel<<<NTILES * 2, 256, GEMM_SMEM>>>(l, bl[l], 0);      // #4 (l=0)
        edge_kernel<<<(NN * 32) / 256, 256>>>(l == 3 ? 1 : 0);
    }

    c128_kernel<<<1, 128>>>(Wa, ba);
    tc_gemm_kernel<<<NTILES * 2, 256, GEMM_SMEM>>>(4, ba, 1);
    head2_kernel<<<(NN * 32) / 256, 256>>>(Wb, bb, x, out);
}

// round 6
// speedup vs baseline: 2.7567x; 1.2435x over previous
#include <cuda_runtime.h>
#include <cuda_bf16.h>
#include <cstdint>

#define NN 100000
#define EE 1600000
#define TILE_M 128
#define NTILES ((NN + TILE_M - 1) / TILE_M)   // 782

typedef uint32_t u32;

// ---------------- scratch (static device globals; no allocations) ----------
__device__ __nv_bfloat16  g_hhi[(NN + 128) * 64];  // node features, bf16 hi part
__device__ __nv_bfloat16  g_hlo[(NN + 128) * 64];  // node features, bf16 lo part
__device__ float          g_pq[NN * 128];  // p (cols 0-63), q (cols 64-127)
__device__ int            g_src[EE];       // int32 source indices
__device__ unsigned       g_gmax[64];      // global max bits (values >= 0)
__device__ float          g_c128[128];     // head constant: g @ Wa[64:128] + ba
__device__ __nv_bfloat16  g_whi[5 * 128 * 64];  // weight hi parts, [n][k] flat
__device__ __nv_bfloat16  g_wlo[5 * 128 * 64];  // weight lo parts

// ---------------- convert (fused gmax zero + dtype detect) ------------------
__global__ void convert_kernel(const int* __restrict__ ei) {
    __shared__ int s64;
    if (blockIdx.x == 0 && threadIdx.x < 64) g_gmax[threadIdx.x] = 0u;
    if (threadIdx.x == 0) {
        // int64 layout => odd words of src row all zero (0<=src<1e5);
        // int32 layout => P(all 64 zero) ~ 1e-320.
        int z = 0;
        for (int i = 0; i < 64; i++) z += (ei[2 * i + 1] == 0) ? 1 : 0;
        s64 = (z == 64) ? 1 : 0;
    }
    __syncthreads();
    int e = blockIdx.x * blockDim.x + threadIdx.x;
    if (e < EE) g_src[e] = s64 ? ei[2 * e] : ei[e];
}

// ---------------- layer 1 (nodes) + fused weight prep (last 5 blocks) ------
// wprep: layers 0-3: Wc[n][k] = (n<64) ? W[k][n]-W[k+64][n] : W[k+64][n-64]
//        layer 4:    Wc[n][k] = Wa[k][n]
__global__ void layer1_kernel(const float* __restrict__ x,
                              const float* __restrict__ W1,
                              const float* __restrict__ b1,
                              const float* __restrict__ Wl0,
                              const float* __restrict__ Wl1,
                              const float* __restrict__ Wl2,
                              const float* __restrict__ Wl3,
                              const float* __restrict__ Wa) {
    if (blockIdx.x >= 25000) {
        int b = blockIdx.x - 25000;
        const float* W = (b == 0) ? Wl0 : (b == 1) ? Wl1 : (b == 2) ? Wl2
                       : (b == 3) ? Wl3 : Wa;
        for (int i = threadIdx.x; i < 8192; i += 256) {
            int n = i >> 6, k = i & 63;
            float wv;
            if (b < 4)
                wv = (n < 64) ? (W[k * 64 + n] - W[(k + 64) * 64 + n])
                              : W[(k + 64) * 64 + (n - 64)];
            else
                wv = W[k * 128 + n];
            __nv_bfloat16 hi = __float2bfloat16(wv);
            __nv_bfloat16 lo = __float2bfloat16(wv - __bfloat162float(hi));
            g_whi[b * 8192 + i] = hi;
            g_wlo[b * 8192 + i] = lo;
        }
        return;
    }
    int tid  = threadIdx.x;
    int t    = tid & 63;
    int node = blockIdx.x * 4 + (tid >> 6);
    if (node >= NN) return;
    float x0 = x[node * 3 + 0], x1 = x[node * 3 + 1], x2 = x[node * 3 + 2];
    float w0 = W1[t],       w1 = W1[64 + t],  w2 = W1[128 + t];
    float w3 = W1[192 + t], w4 = W1[256 + t], w5 = W1[320 + t];
    float q = x0 * w3 + x1 * w4 + x2 * w5;
    float p = b1[t] + x0 * (w0 - w3) + x1 * (w1 - w4) + x2 * (w2 - w5);
    g_pq[node * 128 + t]      = p;
    g_pq[node * 128 + 64 + t] = q;
}

// ---------------- edge max -> bf16 hi/lo output (+ fused global max) --------
__global__ void edge_kernel(int dogmax) {
    __shared__ unsigned sm[64];
    int w    = (blockIdx.x * blockDim.x + threadIdx.x) >> 5;  // grid exact
    int lane = threadIdx.x & 31;
    int s = (lane < 16) ? g_src[w * 16 + lane] : 0;
    float2 m = make_float2(-3.402823466e38f, -3.402823466e38f);
    const float* pq = g_pq;
#pragma unroll
    for (int k = 0; k < 16; k++) {
        int j = __shfl_sync(0xffffffffu, s, k);
        float2 v = *(const float2*)(pq + j * 128 + 64 + lane * 2);
        m.x = fmaxf(m.x, v.x);
        m.y = fmaxf(m.y, v.y);
    }
    float2 p = *(const float2*)(pq + w * 128 + lane * 2);
    float rx = fmaxf(p.x + m.x, 0.f);
    float ry = fmaxf(p.y + m.y, 0.f);
    __nv_bfloat16 h0 = __float2bfloat16(rx);
    __nv_bfloat16 h1 = __float2bfloat16(ry);
    __nv_bfloat16 l0 = __float2bfloat16(rx - __bfloat162float(h0));
    __nv_bfloat16 l1 = __float2bfloat16(ry - __bfloat162float(h1));
    *(__nv_bfloat162*)(g_hhi + w * 64 + lane * 2) = __halves2bfloat162(h0, h1);
    *(__nv_bfloat162*)(g_hlo + w * 64 + lane * 2) = __halves2bfloat162(l0, l1);
    if (dogmax) {
        if (threadIdx.x < 64) sm[threadIdx.x] = 0u;
        __syncthreads();
        atomicMax(&sm[lane * 2],     __float_as_uint(rx));   // r >= 0
        atomicMax(&sm[lane * 2 + 1], __float_as_uint(ry));
        __syncthreads();
        if (threadIdx.x < 64) atomicMax(&g_gmax[threadIdx.x], sm[threadIdx.x]);
    }
}

// ---------------- mma / ldmatrix / cp.async helpers -------------------------
static __device__ __forceinline__ void mma16816(float d[4], const u32 a[4],
                                                const u32 b[2]) {
    asm volatile(
        "mma.sync.aligned.m16n8k16.row.col.f32.bf16.bf16.f32 "
        "{%0,%1,%2,%3}, {%4,%5,%6,%7}, {%8,%9}, {%0,%1,%2,%3};"
        : "+f"(d[0]), "+f"(d[1]), "+f"(d[2]), "+f"(d[3])
        : "r"(a[0]), "r"(a[1]), "r"(a[2]), "r"(a[3]), "r"(b[0]), "r"(b[1]));
}
static __device__ __forceinline__ void ldsm4(u32 r[4], u32 addr) {
    asm volatile("ldmatrix.sync.aligned.m8n8.x4.shared.b16 {%0,%1,%2,%3}, [%4];"
        : "=r"(r[0]), "=r"(r[1]), "=r"(r[2]), "=r"(r[3]) : "r"(addr));
}
static __device__ __forceinline__ u32 smem_u32(const void* p) {
    u32 a;
    asm("{ .reg .u64 t; cvta.to.shared.u64 t, %1; cvt.u32.u64 %0, t; }"
        : "=r"(a) : "l"(p));
    return a;
}
static __device__ __forceinline__ void cpasync16(u32 dst, const void* src) {
    asm volatile("cp.async.cg.shared.global [%0], [%1], 16;"
        :: "r"(dst), "l"(src) : "memory");
}
static __device__ __forceinline__ void cpasync_wait_all() {
    asm volatile("cp.async.commit_group;\n\tcp.async.wait_group 0;" ::: "memory");
}

// ---------------- tensor-core GEMM: h[N,64] @ Wc[64,128] -> g_pq ------------
// Grid = NTILES*2: blockIdx>>1 = node tile (128 rows), blockIdx&1 = N half.
// CTA tile 128M x 64N, 8 warps, warp tile 32M x 32N via m16n8k16 bf16 mma.
// 3-pass hi/lo split: Ahi*Bhi + Alo*Bhi + Ahi*Blo, fp32 accum in regs.
// A and B are PRE-SPLIT bf16 in gmem -> prologue is pure cp.async (no cvt).
// Smem rows padded to 72 bf16 (144 B): ldmatrix phases conflict-free.
// mode 0: bias on cols 0-63.  mode 1: bias g_c128, relu at store.
__global__ void __launch_bounds__(256) tc_gemm_kernel(int layer,
                                                      const float* __restrict__ bias,
                                                      int mode) {
    extern __shared__ unsigned char smem[];
    // sAhi [128][72] @0 (18432B), sAlo @18432, sBhi [64][72] @36864 (9216B),
    // sBlo @46080, bias(f32[64]) @55296
    float* sB = (float*)(smem + 55296);
    int tid = threadIdx.x;
    int nb  = (blockIdx.x >> 1) * TILE_M;
    int ny  = blockIdx.x & 1;

    u32 sbase = smem_u32(smem);

    // B: 64 rows x 64 bf16 (128B = 8 chunks), hi+lo = 1024 chunks
    {
        const char* wh = (const char*)(g_whi + layer * 8192 + ny * 4096);
        const char* wl = (const char*)(g_wlo + layer * 8192 + ny * 4096);
#pragma unroll
        for (int c = tid; c < 1024; c += 256) {
            int half = c >> 9;
            int idx  = c & 511;
            int row = idx >> 3, ch = idx & 7;
            u32 dst = sbase + 36864 + half * 9216 + row * 144 + ch * 16;
            const char* src = (half ? wl : wh) + row * 128 + ch * 16;
            cpasync16(dst, src);
        }
    }
    // A: 128 rows x 64 bf16, hi+lo = 2048 chunks (gmem arrays oversized so the
    // last tile's tail reads are in-bounds; garbage rows masked at store)
    {
        const char* ah = (const char*)(g_hhi + (size_t)nb * 64);
        const char* al = (const char*)(g_hlo + (size_t)nb * 64);
#pragma unroll
        for (int c = tid; c < 2048; c += 256) {
            int half = c >> 10;
            int idx  = c & 1023;
            int row = idx >> 3, ch = idx & 7;
            u32 dst = sbase + half * 18432 + row * 144 + ch * 16;
            const char* src = (half ? al : ah) + row * 128 + ch * 16;
            cpasync16(dst, src);
        }
    }
    if (tid < 64) {
        int col = ny * 64 + tid;
        sB[tid] = (mode == 0) ? ((col < 64) ? bias[col] : 0.f) : g_c128[col];
    }
    cpasync_wait_all();
    __syncthreads();

    int lane = tid & 31;
    int wid  = tid >> 5;
    int wm   = wid & 3;      // rows wm*32..+32
    int wn   = wid >> 2;     // cols (CTA-local) wn*32..+32

    // A frag addr: rows wm*32 + mt*16 + (lane&15), k-col (lane>>4)*8
    u32 aHi = sbase + ((wm * 32 + (lane & 15)) * 72 + (lane >> 4) * 8) * 2;
    u32 aLo = aHi + 18432;
    // B frag addr: lanes -> (n sub-row, k half)
    int brow = wn * 32 + (lane & 7) + (lane >> 4) * 8;
    u32 bHi = sbase + 36864 + (brow * 72 + ((lane >> 3) & 1) * 8) * 2;
    u32 bLo = bHi + 9216;

    float d[2][4][4];
#pragma unroll
    for (int mt = 0; mt < 2; mt++)
#pragma unroll
        for (int nf = 0; nf < 4; nf++)
#pragma unroll
            for (int j = 0; j < 4; j++) d[mt][nf][j] = 0.f;

#pragma unroll
    for (int kk = 0; kk < 4; kk++) {
        int ko = kk * 32;  // 16 bf16 = 32 bytes per k-step
        u32 ah[2][4], al[2][4], bb[2][4];
        ldsm4(ah[0], aHi + ko);
        ldsm4(ah[1], aHi + 2304 + ko);         // +16 rows = 16*144 B
        ldsm4(bb[0], bHi + ko);                // nf 0,1
        ldsm4(bb[1], bHi + 2304 + ko);         // nf 2,3
#pragma unroll
        for (int mt = 0; mt < 2; mt++)
#pragma unroll
            for (int nf = 0; nf < 4; nf++)
                mma16816(d[mt][nf], ah[mt], &bb[nf >> 1][(nf & 1) * 2]);
        ldsm4(al[0], aLo + ko);
        ldsm4(al[1], aLo + 2304 + ko);
#pragma unroll
        for (int mt = 0; mt < 2; mt++)
#pragma unroll
            for (int nf = 0; nf < 4; nf++)
                mma16816(d[mt][nf], al[mt], &bb[nf >> 1][(nf & 1) * 2]);
        ldsm4(bb[0], bLo + ko);
        ldsm4(bb[1], bLo + 2304 + ko);
#pragma unroll
        for (int mt = 0; mt < 2; mt++)
#pragma unroll
            for (int nf = 0; nf < 4; nf++)
                mma16816(d[mt][nf], ah[mt], &bb[nf >> 1][(nf & 1) * 2]);
    }

    // Epilogue
    int r = lane >> 2, q = lane & 3;
#pragma unroll
    for (int mt = 0; mt < 2; mt++) {
        int row0 = nb + wm * 32 + mt * 16 + r;
#pragma unroll
        for (int nf = 0; nf < 4; nf++) {
            int ccol = wn * 32 + nf * 8 + 2 * q;
            int gcol = ny * 64 + ccol;
            float bx = sB[ccol], by = sB[ccol + 1];
            float2 v0 = make_float2(d[mt][nf][0] + bx, d[mt][nf][1] + by);
            float2 v1 = make_float2(d[mt][nf][2] + bx, d[mt][nf][3] + by);
            if (mode == 1) {
                v0.x = fmaxf(v0.x, 0.f); v0.y = fmaxf(v0.y, 0.f);
                v1.x = fmaxf(v1.x, 0.f); v1.y = fmaxf(v1.y, 0.f);
            }
            if (row0 < NN)     *(float2*)(g_pq + row0 * 128 + gcol)       = v0;
            if (row0 + 8 < NN) *(float2*)(g_pq + (row0 + 8) * 128 + gcol) = v1;
        }
    }
}

// ---------------- c128 = ba + g @ Wa[64:128] --------------------------------
__global__ void c128_kernel(const float* __restrict__ Wa,
                            const float* __restrict__ ba) {
    int t = threadIdx.x;  // 128 threads
    float s = ba[t];
#pragma unroll 8
    for (int c = 0; c < 64; c++)
        s += __uint_as_float(g_gmax[c]) * Wa[(64 + c) * 128 + t];
    g_c128[t] = s;
}

// ---------------- head stage 2: out = x + r @ Wb + bb ----------------------
__global__ void head2_kernel(const float* __restrict__ Wb,
                             const float* __restrict__ bb,
                             const float* __restrict__ x,
                             float* __restrict__ out) {
    __shared__ float sWb[384];
    for (int i = threadIdx.x; i < 384; i += 256) sWb[i] = Wb[i];
    __syncthreads();
    int w    = (blockIdx.x * blockDim.x + threadIdx.x) >> 5;
    int lane = threadIdx.x & 31;
    if (w >= NN) return;
    float4 r4 = ((const float4*)(g_pq + w * 128))[lane];
    int t = lane * 4;
    float a0 = r4.x * sWb[t * 3 + 0] + r4.y * sWb[t * 3 + 3] +
               r4.z * sWb[t * 3 + 6] + r4.w * sWb[t * 3 + 9];
    float a1 = r4.x * sWb[t * 3 + 1] + r4.y * sWb[t * 3 + 4] +
               r4.z * sWb[t * 3 + 7] + r4.w * sWb[t * 3 + 10];
    float a2 = r4.x * sWb[t * 3 + 2] + r4.y * sWb[t * 3 + 5] +
               r4.z * sWb[t * 3 + 8] + r4.w * sWb[t * 3 + 11];
#pragma unroll
    for (int off = 16; off > 0; off >>= 1) {
        a0 += __shfl_down_sync(0xffffffffu, a0, off);
        a1 += __shfl_down_sync(0xffffffffu, a1, off);
        a2 += __shfl_down_sync(0xffffffffu, a2, off);
    }
    if (lane == 0) {
        out[w * 3 + 0] = x[w * 3 + 0] + bb[0] + a0;
        out[w * 3 + 1] = x[w * 3 + 1] + bb[1] + a1;
        out[w * 3 + 2] = x[w * 3 + 2] + bb[2] + a2;
    }
}

// ---------------- launch ----------------------------------------------------
extern "C" void kernel_launch(void* const* d_in, const int* in_sizes, int n_in,
                              void* d_out, int out_size) {
    (void)in_sizes; (void)n_in; (void)out_size;
    const float* x  = (const float*)d_in[0];
    const int*   ei = (const int*)d_in[1];
    const float* W1 = (const float*)d_in[2];
    const float* b1 = (const float*)d_in[3];
    const float* Wl[4] = {(const float*)d_in[4], (const float*)d_in[6],
                          (const float*)d_in[8], (const float*)d_in[10]};
    const float* bl[4] = {(const float*)d_in[5], (const float*)d_in[7],
                          (const float*)d_in[9], (const float*)d_in[11]};
    const float* Wa = (const float*)d_in[12];
    const float* ba = (const float*)d_in[13];
    const float* Wb = (const float*)d_in[14];
    const float* bb = (const float*)d_in[15];
    float* out = (float*)d_out;

    const int GEMM_SMEM = 55552;
    static bool attr_set = false;
    if (!attr_set) {
        cudaFuncSetAttribute(tc_gemm_kernel,
                             cudaFuncAttributeMaxDynamicSharedMemorySize,
                             GEMM_SMEM);
        attr_set = true;
    }

    convert_kernel<<<(EE + 255) / 256, 256>>>(ei);                        // #1
    layer1_kernel<<<25005, 256>>>(x, W1, b1, Wl[0], Wl[1], Wl[2], Wl[3], Wa); // #2
    edge_kernel<<<(NN * 32) / 256, 256>>>(0);                             // #3

    for (int l = 0; l < 4; l++) {
        tc_gemm_kernel<<<NTILES * 2, 256, GEMM_SMEM>>>(l, bl[l], 0);      // #4 (l=0)
        edge_kernel<<<(NN * 32) / 256, 256>>>(l == 3 ? 1 : 0);
    }

    c128_kernel<<<1, 128>>>(Wa, ba);
    tc_gemm_kernel<<<NTILES * 2, 256, GEMM_SMEM>>>(4, ba, 1);
    head2_kernel<<<(NN * 32) / 256, 256>>>(Wb, bb, x, out);
}